// round 3
// baseline (speedup 1.0000x reference)
#include <cuda_runtime.h>
#include <cuda_bf16.h>
#include <float.h>

#define NEXP 64
#define TPB  256

__global__ void __launch_bounds__(TPB)
optix_route_kernel(const float* __restrict__ pos,
                   const float* __restrict__ centers,
                   const float* __restrict__ radii,
                   float* __restrict__ out_probs,
                   float* __restrict__ out_ids,
                   int B, int write_ids)
{
    __shared__ float4 sc[NEXP];      // (cx, cy, cz, safe_r)
    __shared__ int    s_uniform;

    const int tid = threadIdx.x;

    // ---- preload centers + safe radii into shared ----
    if (tid < NEXP) {
        float cx = centers[3 * tid + 0];
        float cy = centers[3 * tid + 1];
        float cz = centers[3 * tid + 2];
        float r  = fmaxf(fabsf(radii[tid]), 0.01f);
        sc[tid] = make_float4(cx, cy, cz, r);
    }
    __syncthreads();
    if (tid == 0) {
        float r0 = sc[0].w;
        int u = 1;
        #pragma unroll
        for (int e = 1; e < NEXP; e++) u &= (sc[e].w == r0);
        s_uniform = u;
    }
    __syncthreads();
    const int uniform = s_uniform;

    // ---- phase 1: argmax expert per row ----
    const long long gpos = (long long)blockIdx.x * TPB + tid;
    int id = 0;
    if (gpos < B) {
        const float px = pos[3 * gpos + 0];
        const float py = pos[3 * gpos + 1];
        const float pz = pos[3 * gpos + 2];

        bool need_exact = true;
        if (uniform) {
            // FAST PATH: logit ordering == reverse d2 ordering (uniform radii,
            // correctly-rounded sqrt is weakly monotone). d2 computed with the
            // exact fp32 sequence the reference uses.
            float best = FLT_MAX, best2 = FLT_MAX;
            #pragma unroll
            for (int e = 0; e < NEXP; e++) {
                float4 c = sc[e];
                float dx = __fsub_rn(px, c.x);
                float dy = __fsub_rn(py, c.y);
                float dz = __fsub_rn(pz, c.z);
                float d2 = __fadd_rn(__fadd_rn(__fmul_rn(dx, dx), __fmul_rn(dy, dy)),
                                     __fmul_rn(dz, dz));
                if (d2 < best)       { best2 = best; best = d2; id = e; }
                else if (d2 < best2) { best2 = d2; }
            }
            // Ambiguity margin: tie/band collisions need delta_d2 <~ 3e-7*d2;
            // 4e-6 relative gives 13x headroom. Triggers on ~4e-5 of rows.
            need_exact = (__fsub_rn(best2, best) <= fmaf(best, 4e-6f, 1e-9f));
        }

        if (need_exact) {
            // SLOW PATH (rare, or non-uniform radii): faithful fp32 sequence,
            // two recompute passes (no register array).
            float m = -FLT_MAX;
            #pragma unroll
            for (int e = 0; e < NEXP; e++) {
                float4 c = sc[e];
                float dx = __fsub_rn(px, c.x);
                float dy = __fsub_rn(py, c.y);
                float dz = __fsub_rn(pz, c.z);
                float d2 = __fadd_rn(__fadd_rn(__fmul_rn(dx, dx), __fmul_rn(dy, dy)),
                                     __fmul_rn(dz, dz));
                float dist = __fsqrt_rn(__fadd_rn(d2, 1e-12f));
                float li   = __fmul_rn(10.0f, __fsub_rn(c.w, dist));
                if (li > m) m = li;
            }
            // softmax tie band: exp(l-m) rounds to 1.0f when (m-l) <= 2^-25;
            // argmax(softmax) picks the FIRST index inside that band.
            const float band = 2.9802322e-8f;  // 2^-25
            id = NEXP - 1;
            #pragma unroll
            for (int e = NEXP - 1; e >= 0; e--) {
                float4 c = sc[e];
                float dx = __fsub_rn(px, c.x);
                float dy = __fsub_rn(py, c.y);
                float dz = __fsub_rn(pz, c.z);
                float d2 = __fadd_rn(__fadd_rn(__fmul_rn(dx, dx), __fmul_rn(dy, dy)),
                                     __fmul_rn(dz, dz));
                float dist = __fsqrt_rn(__fadd_rn(d2, 1e-12f));
                float li   = __fmul_rn(10.0f, __fsub_rn(c.w, dist));
                if (__fsub_rn(m, li) <= band) id = e;   // keep earliest qualifying index
            }
        }
    }

    // ---- phase 2a: coalesced zero fill of the 256x64 tile (float4) ----
    const long long rowbase = (long long)blockIdx.x * TPB;
    float4* __restrict__ outv = (float4*)out_probs;   // 16 float4 per row
    const float4 zero4 = make_float4(0.f, 0.f, 0.f, 0.f);
    #pragma unroll
    for (int k = 0; k < 16; k++) {
        long long idx = (long long)k * TPB + tid;     // 0 .. 4095 within tile
        long long grow = rowbase + (idx >> 4);
        if (grow < B) outv[grow * 16 + (idx & 15)] = zero4;
    }

    // orders the zero stores before the scatter within the block
    __syncthreads();

    // ---- phase 2b: scatter the hot 1.0f ----
    if (gpos < B) {
        out_probs[gpos * NEXP + id] = 1.0f;
        if (write_ids) out_ids[gpos] = (float)id;
    }
}

extern "C" void kernel_launch(void* const* d_in, const int* in_sizes, int n_in,
                              void* d_out, int out_size)
{
    const float* pos     = (const float*)d_in[0];   // positions_3d (B,3)
    const float* centers = (const float*)d_in[1];   // centers (64,3)
    const float* radii   = (const float*)d_in[2];   // radii (64,)

    int B = in_sizes[0] / 3;
    float* out_probs = (float*)d_out;
    long long need_ids = (long long)B * (NEXP + 1);
    int write_ids = ((long long)out_size >= need_ids) ? 1 : 0;
    float* out_ids = out_probs + (long long)B * NEXP;

    int grid = (B + TPB - 1) / TPB;
    optix_route_kernel<<<grid, TPB>>>(pos, centers, radii, out_probs, out_ids, B, write_ids);
}

// round 4
// speedup vs baseline: 1.6240x; 1.6240x over previous
#include <cuda_runtime.h>
#include <cuda_bf16.h>
#include <float.h>

#define NEXP 64
#define TPB  256

// Rare exact path: faithful reproduction of the reference fp32 sequence
// (sqrt logits + softmax-tie band). Kept __noinline__ with partial unroll so
// it cannot inflate the main kernel's register count.
__device__ __noinline__ int exact_argmax(float px, float py, float pz,
                                         const float4* __restrict__ sc)
{
    float m = -FLT_MAX;
    #pragma unroll 4
    for (int e = 0; e < NEXP; e++) {
        float4 c = sc[e];
        float dx = __fsub_rn(px, c.x);
        float dy = __fsub_rn(py, c.y);
        float dz = __fsub_rn(pz, c.z);
        float d2 = __fadd_rn(__fadd_rn(__fmul_rn(dx, dx), __fmul_rn(dy, dy)),
                             __fmul_rn(dz, dz));
        float dist = __fsqrt_rn(__fadd_rn(d2, 1e-12f));
        float li   = __fmul_rn(10.0f, __fsub_rn(c.w, dist));
        if (li > m) m = li;
    }
    // softmax tie band: exp(l-m) rounds to 1.0f when (m-l) <= 2^-25, so
    // argmax(softmax) picks the FIRST index inside that band.
    const float band = 2.9802322e-8f;  // 2^-25
    #pragma unroll 4
    for (int e = 0; e < NEXP; e++) {
        float4 c = sc[e];
        float dx = __fsub_rn(px, c.x);
        float dy = __fsub_rn(py, c.y);
        float dz = __fsub_rn(pz, c.z);
        float d2 = __fadd_rn(__fadd_rn(__fmul_rn(dx, dx), __fmul_rn(dy, dy)),
                             __fmul_rn(dz, dz));
        float dist = __fsqrt_rn(__fadd_rn(d2, 1e-12f));
        float li   = __fmul_rn(10.0f, __fsub_rn(c.w, dist));
        if (__fsub_rn(m, li) <= band) return e;
    }
    return NEXP - 1;  // unreachable
}

__global__ void __launch_bounds__(TPB)
optix_route_scatter(const float* __restrict__ pos,
                    const float* __restrict__ centers,
                    const float* __restrict__ radii,
                    float* __restrict__ out_probs,
                    float* __restrict__ out_ids,
                    int B, int write_ids)
{
    __shared__ float4 sc[NEXP];      // (cx, cy, cz, safe_r)
    __shared__ int    s_uniform;

    const int tid = threadIdx.x;

    if (tid < NEXP) {
        float cx = centers[3 * tid + 0];
        float cy = centers[3 * tid + 1];
        float cz = centers[3 * tid + 2];
        float r  = fmaxf(fabsf(radii[tid]), 0.01f);
        sc[tid] = make_float4(cx, cy, cz, r);
    }
    __syncthreads();
    if (tid == 0) {
        float r0 = sc[0].w;
        int u = 1;
        #pragma unroll
        for (int e = 1; e < NEXP; e++) u &= (sc[e].w == r0);
        s_uniform = u;
    }
    __syncthreads();
    const int uniform = s_uniform;

    const long long gpos = (long long)blockIdx.x * TPB + tid;
    if (gpos >= B) return;

    const float px = pos[3 * gpos + 0];
    const float py = pos[3 * gpos + 1];
    const float pz = pos[3 * gpos + 2];

    int  id = 0;
    bool need_exact = true;
    if (uniform) {
        // FAST PATH: uniform radii => logit ordering == reverse d2 ordering
        // (correctly-rounded sqrt is weakly monotone). d2 uses the exact fp32
        // op sequence of the reference.
        float best = FLT_MAX, best2 = FLT_MAX;
        #pragma unroll
        for (int e = 0; e < NEXP; e++) {
            float4 c = sc[e];
            float dx = __fsub_rn(px, c.x);
            float dy = __fsub_rn(py, c.y);
            float dz = __fsub_rn(pz, c.z);
            float d2 = __fadd_rn(__fadd_rn(__fmul_rn(dx, dx), __fmul_rn(dy, dy)),
                                 __fmul_rn(dz, dz));
            if (d2 < best)       { best2 = best; best = d2; id = e; }
            else if (d2 < best2) { best2 = d2; }
        }
        // Tie/band collisions require delta_d2 <~ 3e-7*d2; margin has 13x headroom.
        need_exact = (__fsub_rn(best2, best) <= fmaf(best, 4e-6f, 1e-9f));
    }
    if (need_exact) id = exact_argmax(px, py, pz, sc);

    out_probs[gpos * NEXP + id] = 1.0f;
    if (write_ids) out_ids[gpos] = (float)id;
}

extern "C" void kernel_launch(void* const* d_in, const int* in_sizes, int n_in,
                              void* d_out, int out_size)
{
    const float* pos     = (const float*)d_in[0];   // positions_3d (B,3)
    const float* centers = (const float*)d_in[1];   // centers (64,3)
    const float* radii   = (const float*)d_in[2];   // radii (64,)

    int B = in_sizes[0] / 3;
    float* out_probs = (float*)d_out;
    long long need_ids = (long long)B * (NEXP + 1);
    int write_ids = ((long long)out_size >= need_ids) ? 1 : 0;
    float* out_ids = out_probs + (long long)B * NEXP;

    // Zero the whole output at memcpy-engine/HBM speed; scatter fills the hot
    // entries (and ids) afterwards. Memset node is graph-capturable.
    cudaMemsetAsync(d_out, 0, (size_t)out_size * sizeof(float), 0);

    int grid = (B + TPB - 1) / TPB;
    optix_route_scatter<<<grid, TPB>>>(pos, centers, radii, out_probs, out_ids, B, write_ids);
}

// round 5
// speedup vs baseline: 2.5767x; 1.5866x over previous
#include <cuda_runtime.h>
#include <cuda_bf16.h>
#include <float.h>

#define NEXP 64
#define TPB  256

// Rare exact path: faithful reproduction of the reference fp32 sequence
// (sqrt logits + softmax-tie band). __noinline__ + partial unroll so it never
// inflates the main kernel's register count (R3 lesson: inlining -> 255 regs).
__device__ __noinline__ int exact_argmax(float px, float py, float pz,
                                         const float4* __restrict__ sc)
{
    float m = -FLT_MAX;
    #pragma unroll 4
    for (int e = 0; e < NEXP; e++) {
        float4 c = sc[e];
        float dx = __fsub_rn(px, c.x);
        float dy = __fsub_rn(py, c.y);
        float dz = __fsub_rn(pz, c.z);
        float d2 = __fadd_rn(__fadd_rn(__fmul_rn(dx, dx), __fmul_rn(dy, dy)),
                             __fmul_rn(dz, dz));
        float dist = __fsqrt_rn(__fadd_rn(d2, 1e-12f));
        float li   = __fmul_rn(10.0f, __fsub_rn(c.w, dist));
        if (li > m) m = li;
    }
    // softmax tie band: exp(l-m) rounds to 1.0f when (m-l) <= 2^-25, so
    // argmax(softmax) picks the FIRST index inside that band.
    const float band = 2.9802322e-8f;  // 2^-25
    #pragma unroll 4
    for (int e = 0; e < NEXP; e++) {
        float4 c = sc[e];
        float dx = __fsub_rn(px, c.x);
        float dy = __fsub_rn(py, c.y);
        float dz = __fsub_rn(pz, c.z);
        float d2 = __fadd_rn(__fadd_rn(__fmul_rn(dx, dx), __fmul_rn(dy, dy)),
                             __fmul_rn(dz, dz));
        float dist = __fsqrt_rn(__fadd_rn(d2, 1e-12f));
        float li   = __fmul_rn(10.0f, __fsub_rn(c.w, dist));
        if (__fsub_rn(m, li) <= band) return e;
    }
    return NEXP - 1;  // unreachable
}

__global__ void __launch_bounds__(TPB)
optix_route_fused(const float* __restrict__ pos,
                  const float* __restrict__ centers,
                  const float* __restrict__ radii,
                  float* __restrict__ out_probs,
                  float* __restrict__ out_ids,
                  int B, int write_ids)
{
    __shared__ float4 sc[NEXP];      // (cx, cy, cz, safe_r)
    __shared__ int    sids[TPB];
    __shared__ int    s_uniform;

    const int tid = threadIdx.x;

    if (tid < NEXP) {
        float cx = centers[3 * tid + 0];
        float cy = centers[3 * tid + 1];
        float cz = centers[3 * tid + 2];
        float r  = fmaxf(fabsf(radii[tid]), 0.01f);
        sc[tid] = make_float4(cx, cy, cz, r);
    }
    __syncthreads();
    if (tid == 0) {
        float r0 = sc[0].w;
        int u = 1;
        #pragma unroll
        for (int e = 1; e < NEXP; e++) u &= (sc[e].w == r0);
        s_uniform = u;
    }
    __syncthreads();
    const int uniform = s_uniform;

    // ---- phase 1: argmax per row ----
    const long long gpos = (long long)blockIdx.x * TPB + tid;
    int id = 0;
    if (gpos < B) {
        const float px = pos[3 * gpos + 0];
        const float py = pos[3 * gpos + 1];
        const float pz = pos[3 * gpos + 2];

        bool need_exact = true;
        if (uniform) {
            // FAST PATH: uniform radii => logit order == reverse d2 order.
            // FMA-contracted d2 (cheaper than the reference sequence); its
            // <=~2.4e-7 relative deviation is absorbed by the margin below.
            float best = FLT_MAX, best2 = FLT_MAX;
            #pragma unroll
            for (int e = 0; e < NEXP; e++) {
                float4 c = sc[e];
                float dx = px - c.x;
                float dy = py - c.y;
                float dz = pz - c.z;
                float d2 = __fmaf_rn(dx, dx, __fmaf_rn(dy, dy, dz * dz));
                // branch-free best/best2/id tracking (FMNMX + FSETP/SEL)
                float mx = fmaxf(best, d2);
                best2 = fminf(best2, mx);
                id    = (d2 < best) ? e : id;
                best  = fminf(best, d2);
            }
            // margin covers FMA-vs-reference deviation + sqrt/band collisions
            need_exact = (best2 - best <= __fmaf_rn(best, 2e-6f, 1e-9f));
        }
        if (need_exact) id = exact_argmax(px, py, pz, sc);
    }
    sids[tid] = id;
    __syncthreads();

    // ---- phase 2a: coalesced zero fill of this block's 256x64 tile ----
    const long long rowbase = (long long)blockIdx.x * TPB;
    float4* __restrict__ outv = (float4*)out_probs;   // 16 float4 per row
    const float4 zero4 = make_float4(0.f, 0.f, 0.f, 0.f);
    #pragma unroll
    for (int k = 0; k < 16; k++) {
        long long idx = (long long)k * TPB + tid;     // 0..4095 in tile
        long long grow = rowbase + (idx >> 4);
        if (grow < B) outv[grow * 16 + (idx & 15)] = zero4;
    }

    // __syncthreads orders prior global stores before subsequent block accesses
    __syncthreads();

    // ---- phase 2b: scatter the hot 1.0f ----
    if (gpos < B) {
        out_probs[gpos * NEXP + id] = 1.0f;
        if (write_ids) out_ids[gpos] = (float)id;
    }
}

extern "C" void kernel_launch(void* const* d_in, const int* in_sizes, int n_in,
                              void* d_out, int out_size)
{
    const float* pos     = (const float*)d_in[0];   // positions_3d (B,3)
    const float* centers = (const float*)d_in[1];   // centers (64,3)
    const float* radii   = (const float*)d_in[2];   // radii (64,)

    int B = in_sizes[0] / 3;
    float* out_probs = (float*)d_out;
    long long need_ids = (long long)B * (NEXP + 1);
    int write_ids = ((long long)out_size >= need_ids) ? 1 : 0;
    float* out_ids = out_probs + (long long)B * NEXP;

    int grid = (B + TPB - 1) / TPB;
    optix_route_fused<<<grid, TPB>>>(pos, centers, radii, out_probs, out_ids, B, write_ids);
}